// round 1
// baseline (speedup 1.0000x reference)
#include <cuda_runtime.h>
#include <stdint.h>

#define N_LABELS 1000

// Modes:
//  0: mask written as float32 at out + n        (out_size == 2*n)
//  1: mask written as int16  at (short*)(out+n) (out_size == n + n/2, i16 packed in f32 buffer)
//  2: no mask output (out_size == n)
template <int MODE>
__global__ void __launch_bounds__(256)
vessel_fuse_kernel(const int4* __restrict__ labels4,
                   const float4* __restrict__ par4,
                   const int* __restrict__ keep_mask,
                   const float* __restrict__ intensity_lut,
                   float4* __restrict__ out4,
                   float4* __restrict__ maskf4,
                   uint2* __restrict__ mask16x4,
                   int nv,           // number of vec4 groups
                   int n)            // total voxels
{
    __shared__ float         s_mult[N_LABELS];
    __shared__ unsigned char s_msk[N_LABELS];

    // Build effective LUT once per block:
    //   kept vessel (label>0, keep_mask>0): mult = intensity, mask = 1
    //   otherwise (background or pruned):   mult = 1.0,       mask = 0
    for (int i = threadIdx.x; i < N_LABELS; i += blockDim.x) {
        bool k = (i > 0) && (keep_mask[i] > 0);
        s_mult[i] = k ? __ldg(&intensity_lut[i]) : 1.0f;
        s_msk[i]  = k ? 1 : 0;
    }
    __syncthreads();

    const int stride = gridDim.x * blockDim.x;
    int idx = blockIdx.x * blockDim.x + threadIdx.x;

    for (int i = idx; i < nv; i += stride) {
        int4   L = labels4[i];
        float4 P = par4[i];

        float m0 = s_mult[L.x];
        float m1 = s_mult[L.y];
        float m2 = s_mult[L.z];
        float m3 = s_mult[L.w];

        float4 O;
        O.x = P.x * m0;
        O.y = P.y * m1;
        O.z = P.z * m2;
        O.w = P.w * m3;
        out4[i] = O;

        if (MODE == 0) {
            float4 M;
            M.x = (float)s_msk[L.x];
            M.y = (float)s_msk[L.y];
            M.z = (float)s_msk[L.z];
            M.w = (float)s_msk[L.w];
            maskf4[i] = M;
        } else if (MODE == 1) {
            uint2 mm;
            mm.x = (uint32_t)s_msk[L.x] | ((uint32_t)s_msk[L.y] << 16);
            mm.y = (uint32_t)s_msk[L.z] | ((uint32_t)s_msk[L.w] << 16);
            mask16x4[i] = mm;
        }
    }

    // Scalar tail (n not divisible by 4) — handled by first few global threads.
    int tail = n - nv * 4;
    if (idx < tail) {
        int j = nv * 4 + idx;
        int lab = ((const int*)labels4)[j];
        float p = ((const float*)par4)[j];
        ((float*)out4)[j] = p * s_mult[lab];
        if (MODE == 0) ((float*)maskf4)[j] = (float)s_msk[lab];
        else if (MODE == 1) ((short*)mask16x4)[j] = (short)s_msk[lab];
    }
}

extern "C" void kernel_launch(void* const* d_in, const int* in_sizes, int n_in,
                              void* d_out, int out_size)
{
    const int*   labels = (const int*)d_in[0];
    const int*   keep   = (const int*)d_in[1];
    const float* lut    = (const float*)d_in[2];
    const float* par    = (const float*)d_in[3];
    float*       out    = (float*)d_out;

    const int n  = in_sizes[0];       // D^3 voxels
    const int nv = n / 4;

    const int threads = 256;
    int blocks = (nv + threads - 1) / threads;
    const int max_blocks = 148 * 32;  // full-chip wave-friendly grid-stride
    if (blocks > max_blocks) blocks = max_blocks;
    if (blocks < 1) blocks = 1;

    const int4*   labels4 = (const int4*)labels;
    const float4* par4    = (const float4*)par;
    float4*       out4    = (float4*)out;

    if (out_size >= 2 * n) {
        float4* maskf4 = (float4*)(out + n);
        vessel_fuse_kernel<0><<<blocks, threads>>>(labels4, par4, keep, lut,
                                                   out4, maskf4, nullptr, nv, n);
    } else if (out_size >= n + n / 2) {
        uint2* mask16x4 = (uint2*)(out + n);
        vessel_fuse_kernel<1><<<blocks, threads>>>(labels4, par4, keep, lut,
                                                   out4, nullptr, mask16x4, nv, n);
    } else {
        vessel_fuse_kernel<2><<<blocks, threads>>>(labels4, par4, keep, lut,
                                                   out4, nullptr, nullptr, nv, n);
    }
}